// round 14
// baseline (speedup 1.0000x reference)
#include <cuda_runtime.h>
#include <math.h>
#include <stdint.h>

#define TOK 4096            // 4 * 1024
#define QLEN 1024

typedef unsigned long long ull;

// ---------------- packed f32x2 helpers --------------------------------------
__device__ __forceinline__ ull fma2(ull a, ull b, ull c) {
    ull d; asm("fma.rn.f32x2 %0, %1, %2, %3;" : "=l"(d) : "l"(a), "l"(b), "l"(c));
    return d;
}
__device__ __forceinline__ ull mul2(ull a, ull b) {
    ull d; asm("mul.rn.f32x2 %0, %1, %2;" : "=l"(d) : "l"(a), "l"(b));
    return d;
}
__device__ __forceinline__ ull add2(ull a, ull b) {
    ull d; asm("add.rn.f32x2 %0, %1, %2;" : "=l"(d) : "l"(a), "l"(b));
    return d;
}
__device__ __forceinline__ ull packf2(float lo, float hi) {
    ull r; asm("mov.b64 %0, {%1, %2};" : "=l"(r) : "f"(lo), "f"(hi));
    return r;
}
__device__ __forceinline__ void unpackf2(ull v, float& lo, float& hi) {
    asm("mov.b64 {%0, %1}, %2;" : "=f"(lo), "=f"(hi) : "l"(v));
}
__device__ __forceinline__ float ex2(float x) {
    float y; asm("ex2.approx.ftz.f32 %0, %1;" : "=f"(y) : "f"(x));
    return y;
}

// ---------------- cp.async helpers ------------------------------------------
__device__ __forceinline__ void cpa16(uint32_t dst, const void* src, int bytes) {
    asm volatile("cp.async.cg.shared.global [%0], [%1], 16, %2;"
                 :: "r"(dst), "l"(src), "r"(bytes));
}
__device__ __forceinline__ void cpa4(uint32_t dst, const void* src, int bytes) {
    asm volatile("cp.async.ca.shared.global [%0], [%1], 4, %2;"
                 :: "r"(dst), "l"(src), "r"(bytes));
}
__device__ __forceinline__ void cpa_commit() {
    asm volatile("cp.async.commit_group;" ::: "memory");
}
__device__ __forceinline__ void cpa_waitall() {
    asm volatile("cp.async.wait_group 0;" ::: "memory");
}
__device__ __forceinline__ void cpa_wait1() {
    asm volatile("cp.async.wait_group 1;" ::: "memory");
}

// ---------------- scratch (no allocations allowed) ----------------
__device__ float g_qkv0[3][TOK * 192];   // Q,K,V for MHA0
__device__ float g_qkv1[3][TOK * 66];    // Q,K,V for MHA1
__device__ int   g_cIdx[2][4][1024];
__device__ int   g_cnt[2][4];
__device__ float g_c0[TOK * 192];
__device__ float g_c1[TOK * 66];

// ---------------- 128-thread mask compaction (runs inside gemm launch) ------
__device__ void compact_body(const int* __restrict__ m, int which, int b)
{
    int t = threadIdx.x;              // 128 threads, 8 elems each
    int base8 = t * 8;
    unsigned bits = 0;
#pragma unroll
    for (int i = 0; i < 8; i++)
        bits |= ((m[b * QLEN + base8 + i] != 0) ? 1u : 0u) << i;
    int pc = __popc(bits);

    int lane = t & 31, w = t >> 5;
    int pre = pc;
#pragma unroll
    for (int off = 1; off < 32; off <<= 1) {
        int nv = __shfl_up_sync(0xffffffffu, pre, off);
        if (lane >= off) pre += nv;
    }
    __shared__ int ws[4];
    if (lane == 31) ws[w] = pre;
    __syncthreads();
    int wbase = 0;
#pragma unroll
    for (int i = 0; i < 4; i++)
        if (i < w) wbase += ws[i];
    int ex = wbase + pre - pc;        // exclusive prefix for this thread
#pragma unroll
    for (int i = 0; i < 8; i++)
        if ((bits >> i) & 1)
            g_cIdx[which][b][ex++] = base8 + i;
    if (t == 0)
        g_cnt[which][b] = ws[0] + ws[1] + ws[2] + ws[3];
}

// ---------------- multi-job GEMM (cp.async 3-stage, 64x64 tile, 128 thr) ----
// Per-thread 4 rows x 8 cols (two 4-col runs), 16B SMEM loads for A and B.
struct GemmJob  { const float* A; const float* W; const float* B; float* C;
                  int N; int K; float scale; };
struct GemmJobs { GemmJob j[6]; const int* m0; const int* m1; };

__global__ __launch_bounds__(128) void gemm_cp(GemmJobs js)
{
    if (blockIdx.z == 6) {            // compaction slice (QKV launch only)
        if (blockIdx.x == 0 && blockIdx.y < 8) {
            int which = blockIdx.y >> 2, b = blockIdx.y & 3;
            compact_body(which ? js.m1 : js.m0, which, b);
        }
        return;
    }

    GemmJob jb = js.j[blockIdx.z];
    const int N = jb.N, K = jb.K;
    const int cBase = blockIdx.x * 64;
    if (cBase >= N) return;
    const int rBase = blockIdx.y * 64;
    const float* __restrict__ A    = jb.A;
    const float* __restrict__ W    = jb.W;
    const float* __restrict__ bias = jb.B;
    float* __restrict__ C          = jb.C;
    const float scale              = jb.scale;
    const bool aligned = ((K & 3) == 0) && ((N & 3) == 0);

    __shared__ __align__(16) float sA[3][64][36];   // [buf][row][k] (pad 36)
    __shared__ __align__(16) float sB[3][32][68];   // [buf][k][col] (pad 68)

    const int tt = threadIdx.x;
    const int tx = tt & 7;          // 8 col groups
    const int ty = tt >> 3;         // 16 row groups of 4

    uint32_t aB = (uint32_t)__cvta_generic_to_shared(&sA[0][0][0]);
    uint32_t bB = (uint32_t)__cvta_generic_to_shared(&sB[0][0][0]);

    // 16B-chunk fill: requires K%4==0 and N%4==0
    auto fill_vec = [&](int k0, int buf) {
#pragma unroll
        for (int i = 0; i < 4; i++) {       // A: 64 rows x 8 chunks
            int ci = tt + i * 128;
            int row = ci >> 3, kc = ci & 7;
            int kg = k0 + kc * 4;
            uint32_t dst = aB + ((buf * 64 + row) * 36 + kc * 4) * 4;
            const float* src = A + (size_t)(rBase + row) * K + kg;
            int bytes = min(max(K - kg, 0), 4) * 4;
            cpa16(dst, src, bytes);
        }
#pragma unroll
        for (int i = 0; i < 4; i++) {       // B: 32 k x 16 chunks
            int ci = tt + i * 128;
            int kr = ci >> 4, cc = ci & 15;
            int kg = k0 + kr;
            int cg = cBase + cc * 4;
            uint32_t dst = bB + ((buf * 32 + kr) * 68 + cc * 4) * 4;
            const float* src = W + (size_t)kg * N + cg;
            int bytes = (kg < K) ? min(max(N - cg, 0), 4) * 4 : 0;
            cpa16(dst, src, bytes);
        }
        cpa_commit();
    };
    // 4B-per-element fill: always aligned (float tensors)
    auto fill_sca = [&](int k0, int buf) {
#pragma unroll
        for (int i = 0; i < 16; i++) {      // A: 2048 elems
            int ci = tt + i * 128;
            int row = ci >> 5, kc = ci & 31;
            int kg = k0 + kc;
            uint32_t dst = aB + ((buf * 64 + row) * 36 + kc) * 4;
            const float* src = A + (size_t)(rBase + row) * K + kg;
            cpa4(dst, src, (kg < K) ? 4 : 0);
        }
#pragma unroll
        for (int i = 0; i < 16; i++) {      // B: 2048 elems
            int ci = tt + i * 128;
            int kr = ci >> 6, cc = ci & 63;
            int kg = k0 + kr;
            int cg = cBase + cc;
            uint32_t dst = bB + ((buf * 32 + kr) * 68 + cc) * 4;
            const float* src = W + (size_t)kg * N + cg;
            cpa4(dst, src, (kg < K && cg < N) ? 4 : 0);
        }
        cpa_commit();
    };
    auto fill = [&](int k0, int buf) {
        if (aligned) fill_vec(k0, buf); else fill_sca(k0, buf);
    };

    ull acc2[4][4];                 // [row][colpair]
#pragma unroll
    for (int r = 0; r < 4; r++)
#pragma unroll
        for (int j = 0; j < 4; j++) acc2[r][j] = 0ull;

    const int ntk = (K + 31) >> 5;
    // 3-stage pipeline: two tiles in flight
    fill(0, 0);
    if (ntk > 1) fill(32, 1);
    int mod3 = 0;                   // t % 3
    for (int t = 0; t < ntk; t++) {
        if (t + 1 < ntk) cpa_wait1(); else cpa_waitall();
        __syncthreads();
        if (t + 2 < ntk) {
            int nb = mod3 + 2; if (nb >= 3) nb -= 3;
            fill((t + 2) * 32, nb);
        }
        const int buf = mod3;
#pragma unroll
        for (int g = 0; g < 8; g++) {       // 4 k per group
            float4 av[4];
#pragma unroll
            for (int r = 0; r < 4; r++)
                av[r] = *(const float4*)&sA[buf][ty * 4 + r][g * 4];
#pragma unroll
            for (int kk = 0; kk < 4; kk++) {
                ulonglong2 b0 = *(const ulonglong2*)&sB[buf][g * 4 + kk][4 * tx];
                ulonglong2 b1 = *(const ulonglong2*)&sB[buf][g * 4 + kk][4 * tx + 32];
                ull bp[4] = {b0.x, b0.y, b1.x, b1.y};
                ull ad[4];
#pragma unroll
                for (int r = 0; r < 4; r++) {
                    float a = (kk == 0) ? av[r].x : (kk == 1) ? av[r].y
                            : (kk == 2) ? av[r].z : av[r].w;
                    ad[r] = packf2(a, a);
                }
#pragma unroll
                for (int r = 0; r < 4; r++)
#pragma unroll
                    for (int j = 0; j < 4; j++)
                        acc2[r][j] = fma2(ad[r], bp[j], acc2[r][j]);
            }
        }
        if (++mod3 == 3) mod3 = 0;
    }

#pragma unroll
    for (int r = 0; r < 4; r++) {
        int row = rBase + ty * 4 + r;
#pragma unroll
        for (int j = 0; j < 4; j++) {
            int cg = cBase + 4 * tx + (j >> 1) * 32 + (j & 1) * 2;
            if (cg + 1 < N) {
                float lo, hi;
                unpackf2(acc2[r][j], lo, hi);
                float2 o = make_float2((lo + bias[cg]) * scale,
                                       (hi + bias[cg + 1]) * scale);
                *(float2*)&C[(size_t)row * N + cg] = o;
            } else if (cg < N) {
                float lo, hi;
                unpackf2(acc2[r][j], lo, hi);
                C[(size_t)row * N + cg] = (lo + bias[cg]) * scale;
            }
        }
    }
}

// ---------------- attention inner tile (packed, no running max) -------------
template <int DPHP, int TQ, bool TAIL>
__device__ __forceinline__ void attn_tile(
    const float* __restrict__ sK, const float* __restrict__ sV,
    int kbase, int cnt,
    ull (&q2)[TQ][DPHP / 2], ull (&acc2)[TQ][DPHP / 2], float (&l)[TQ])
{
#pragma unroll 2
    for (int k = 0; k < 128; k++) {
        ull kr[DPHP / 2], vr[DPHP / 2];
        const ulonglong2* pk = (const ulonglong2*)(sK + k * DPHP);
        const ulonglong2* pv = (const ulonglong2*)(sV + k * DPHP);
#pragma unroll
        for (int i = 0; i < DPHP / 4; i++) {
            ulonglong2 a = pk[i]; kr[2 * i] = a.x; kr[2 * i + 1] = a.y;
            ulonglong2 b = pv[i]; vr[2 * i] = b.x; vr[2 * i + 1] = b.y;
        }
        float bias = 0.f;
        if (TAIL) bias = (kbase + k < cnt) ? 0.f : -1e30f;
        float p[TQ];
#pragma unroll
        for (int j = 0; j < TQ; j++) {
            ull d0 = mul2(q2[j][0], kr[0]);
            ull d1 = mul2(q2[j][1], kr[1]);
#pragma unroll
            for (int i = 2; i < DPHP / 2; i += 2) {
                d0 = fma2(q2[j][i],     kr[i],     d0);
                d1 = fma2(q2[j][i + 1], kr[i + 1], d1);
            }
            float lo, hi;
            unpackf2(add2(d0, d1), lo, hi);
            float dot = lo + hi;
            if (TAIL) dot += bias;
            p[j] = ex2(dot);
            l[j] += p[j];
        }
#pragma unroll
        for (int j = 0; j < TQ; j++) {
            ull pp = packf2(p[j], p[j]);
#pragma unroll
            for (int i = 0; i < DPHP / 2; i++)
                acc2[j][i] = fma2(pp, vr[i], acc2[j][i]);
        }
    }
}

// ---------------- flash attention (cp.async tile loads) ---------------------
template <int DPH, int DPHP, int TQ, int NH>
__device__ __forceinline__ void attn_body(
    int idx, const float* __restrict__ Q,
    const float* __restrict__ Ksrc, const float* __restrict__ Vsrc,
    const int* __restrict__ cIdx, const int* __restrict__ cntArr,
    float* __restrict__ C)
{
    constexpr int BH = 4 * NH;
    const int dim = NH * DPH;
    const int bh = idx % BH;
    const int qt = idx / BH;            // 4 query tiles of 256
    const int b = bh / NH, h = bh % NH;
    const int qi0 = (qt * 128 + threadIdx.x) * TQ;

    const int cnt = cntArr[b];
    const int nt = (cnt + 127) >> 7;

    __shared__ __align__(16) float sK[2][128 * DPHP];
    __shared__ __align__(16) float sV[2][128 * DPHP];

    uint32_t kB = (uint32_t)__cvta_generic_to_shared(&sK[0][0]);
    uint32_t vB = (uint32_t)__cvta_generic_to_shared(&sV[0][0]);

    const int kk = threadIdx.x;

    // pre-zero pad slots (DPH < DPHP): written once, never overwritten
    if constexpr (DPH != DPHP) {
#pragma unroll
        for (int bf = 0; bf < 2; bf++)
#pragma unroll
            for (int d = DPH; d < DPHP; d += 2) {
                *(float2*)&sK[bf][kk * DPHP + d] = make_float2(0.f, 0.f);
                *(float2*)&sV[bf][kk * DPHP + d] = make_float2(0.f, 0.f);
            }
    }

    auto afill = [&](int tile, int buf) {
        int j = tile * 128 + kk;
        int src = (j < cnt) ? cIdx[b * 1024 + j] : 0;
        const char* kp = (const char*)(Ksrc + (size_t)(b * QLEN + src) * dim + h * DPH);
        const char* vp = (const char*)(Vsrc + (size_t)(b * QLEN + src) * dim + h * DPH);
        uint32_t dk = kB + (buf * 128 + kk) * DPHP * 4;
        uint32_t dv = vB + (buf * 128 + kk) * DPHP * 4;
        if constexpr (DPH == 12) {
            // dim=192: row stride 768B, h*48B -> 16B-aligned
#pragma unroll
            for (int i = 0; i < 3; i++) {
                cpa16(dk + i * 16, kp + i * 16, 16);
                cpa16(dv + i * 16, vp + i * 16, 16);
            }
        } else {
            // dim=66: only 4B alignment guaranteed
#pragma unroll
            for (int i = 0; i < DPH; i++) {
                cpa4(dk + i * 4, kp + i * 4, 4);
                cpa4(dv + i * 4, vp + i * 4, 4);
            }
        }
        cpa_commit();
    };

    ull q2[TQ][DPHP / 2];
#pragma unroll
    for (int j = 0; j < TQ; j++) {
        const float* qp = Q + (size_t)(b * QLEN + qi0 + j) * dim + h * DPH;
        float qv[DPHP];
#pragma unroll
        for (int d = 0; d < DPH; d += 2) {
            float2 v2 = *(const float2*)(qp + d);
            qv[d] = v2.x; qv[d + 1] = v2.y;
        }
#pragma unroll
        for (int d = DPH; d < DPHP; d++) qv[d] = 0.f;
#pragma unroll
        for (int i = 0; i < DPHP / 2; i++)
            q2[j][i] = packf2(qv[2 * i], qv[2 * i + 1]);
    }

    float l[TQ];
    ull acc2[TQ][DPHP / 2];
#pragma unroll
    for (int j = 0; j < TQ; j++) {
        l[j] = 0.f;
#pragma unroll
        for (int i = 0; i < DPHP / 2; i++) acc2[j][i] = 0ull;
    }

    afill(0, 0);
    int cur = 0;
    for (int tt = 0; tt < nt; tt++) {
        cpa_waitall();
        __syncthreads();
        if (tt + 1 < nt) afill(tt + 1, cur ^ 1);
        if (tt == nt - 1)
            attn_tile<DPHP, TQ, true >(sK[cur], sV[cur], tt * 128, cnt, q2, acc2, l);
        else
            attn_tile<DPHP, TQ, false>(sK[cur], sV[cur], tt * 128, cnt, q2, acc2, l);
        cur ^= 1;
    }

    // normalize + direct write to context in (b, q, dim) layout
#pragma unroll
    for (int j = 0; j < TQ; j++) {
        float inv = 1.f / l[j];
        float* cp = C + (size_t)(b * QLEN + qi0 + j) * dim + h * DPH;
#pragma unroll
        for (int i = 0; i < DPH / 2; i++) {
            float lo, hi;
            unpackf2(acc2[j][i], lo, hi);
            *(float2*)(cp + 2 * i) = make_float2(lo * inv, hi * inv);
        }
    }
}

#define NB0 (64 * 4)    // 256
#define NB1 (44 * 4)    // 176

__global__ __launch_bounds__(128) void attn_both()
{
    int bx = blockIdx.x;
    if (bx < NB0)
        attn_body<12, 12, 2, 16>(bx, g_qkv0[0], g_qkv0[1], g_qkv0[2],
                                 &g_cIdx[0][0][0], &g_cnt[0][0], g_c0);
    else
        attn_body<6, 8, 2, 11>(bx - NB0, g_qkv1[0], g_qkv1[1], g_qkv1[2],
                               &g_cIdx[1][0][0], &g_cnt[1][0], g_c1);
}

// ---------------- launch ----------------------------------------------------
extern "C" void kernel_launch(void* const* d_in, const int* in_sizes, int n_in,
                              void* d_out, int out_size)
{
    const float* x     = (const float*)d_in[0];
    const float* y     = (const float*)d_in[1];
    const int*   mask0 = (const int*)d_in[2];
    const int*   mask1 = (const int*)d_in[3];
    const float* q0_w = (const float*)d_in[4],  *q0_b = (const float*)d_in[5];
    const float* k0_w = (const float*)d_in[6],  *k0_b = (const float*)d_in[7];
    const float* v0_w = (const float*)d_in[8],  *v0_b = (const float*)d_in[9];
    const float* o0_w = (const float*)d_in[10], *o0_b = (const float*)d_in[11];
    const float* q1_w = (const float*)d_in[12], *q1_b = (const float*)d_in[13];
    const float* k1_w = (const float*)d_in[14], *k1_b = (const float*)d_in[15];
    const float* v1_w = (const float*)d_in[16], *v1_b = (const float*)d_in[17];
    const float* o1_w = (const float*)d_in[18], *o1_b = (const float*)d_in[19];

    float* out0 = (float*)d_out;
    float* out1 = out0 + (size_t)TOK * 192;

    float *qkv0, *qkv1, *c0, *c1;
    cudaGetSymbolAddress((void**)&qkv0, g_qkv0);
    cudaGetSymbolAddress((void**)&qkv1, g_qkv1);
    cudaGetSymbolAddress((void**)&c0, g_c0);
    cudaGetSymbolAddress((void**)&c1, g_c1);

    const float LOG2E = 1.4426950408889634f;
    const float s0 = LOG2E / sqrtf(12.0f);
    const float s1 = LOG2E / sqrtf(6.0f);

    // fused QKV projections for both MHAs (6 jobs) + compaction slice (z=6)
    GemmJobs jq;
    jq.j[0] = { x, q0_w, q0_b, qkv0,                         192, 192, s0 };
    jq.j[1] = { x, k0_w, k0_b, qkv0 + (size_t)TOK * 192,     192, 192, 1.f };
    jq.j[2] = { x, v0_w, v0_b, qkv0 + (size_t)2 * TOK * 192, 192, 192, 1.f };
    jq.j[3] = { y, q1_w, q1_b, qkv1,                         66,  66,  s1 };
    jq.j[4] = { y, k1_w, k1_b, qkv1 + (size_t)TOK * 66,      66,  66,  1.f };
    jq.j[5] = { y, v1_w, v1_b, qkv1 + (size_t)2 * TOK * 66,  66,  66,  1.f };
    jq.m0 = mask0; jq.m1 = mask1;
    gemm_cp<<<dim3(3, 64, 7), 128>>>(jq);

    // fused attention (both MHAs), cp.async pipelined
    attn_both<<<NB0 + NB1, 128>>>();

    // fused output projections
    GemmJobs jo;
    jo.j[0] = { c0, o0_w, o0_b, out0, 192, 192, 1.f };
    jo.j[1] = { c1, o1_w, o1_b, out1, 66,  66,  1.f };
    jo.j[2] = jo.j[0]; jo.j[3] = jo.j[0]; jo.j[4] = jo.j[0]; jo.j[5] = jo.j[0];
    jo.m0 = mask0; jo.m1 = mask1;
    gemm_cp<<<dim3(3, 64, 2), 128>>>(jo);
}

// round 15
// speedup vs baseline: 1.0128x; 1.0128x over previous
#include <cuda_runtime.h>
#include <math.h>
#include <stdint.h>

#define TOK 4096            // 4 * 1024
#define QLEN 1024

typedef unsigned long long ull;

// ---------------- packed f32x2 helpers --------------------------------------
__device__ __forceinline__ ull fma2(ull a, ull b, ull c) {
    ull d; asm("fma.rn.f32x2 %0, %1, %2, %3;" : "=l"(d) : "l"(a), "l"(b), "l"(c));
    return d;
}
__device__ __forceinline__ ull mul2(ull a, ull b) {
    ull d; asm("mul.rn.f32x2 %0, %1, %2;" : "=l"(d) : "l"(a), "l"(b));
    return d;
}
__device__ __forceinline__ ull add2(ull a, ull b) {
    ull d; asm("add.rn.f32x2 %0, %1, %2;" : "=l"(d) : "l"(a), "l"(b));
    return d;
}
__device__ __forceinline__ ull packf2(float lo, float hi) {
    ull r; asm("mov.b64 %0, {%1, %2};" : "=l"(r) : "f"(lo), "f"(hi));
    return r;
}
__device__ __forceinline__ void unpackf2(ull v, float& lo, float& hi) {
    asm("mov.b64 {%0, %1}, %2;" : "=f"(lo), "=f"(hi) : "l"(v));
}
__device__ __forceinline__ float ex2(float x) {
    float y; asm("ex2.approx.ftz.f32 %0, %1;" : "=f"(y) : "f"(x));
    return y;
}

// ---------------- cp.async helpers ------------------------------------------
__device__ __forceinline__ void cpa16(uint32_t dst, const void* src, int bytes) {
    asm volatile("cp.async.cg.shared.global [%0], [%1], 16, %2;"
                 :: "r"(dst), "l"(src), "r"(bytes));
}
__device__ __forceinline__ void cpa4(uint32_t dst, const void* src, int bytes) {
    asm volatile("cp.async.ca.shared.global [%0], [%1], 4, %2;"
                 :: "r"(dst), "l"(src), "r"(bytes));
}
__device__ __forceinline__ void cpa_commit() {
    asm volatile("cp.async.commit_group;" ::: "memory");
}
__device__ __forceinline__ void cpa_waitall() {
    asm volatile("cp.async.wait_group 0;" ::: "memory");
}

// ---------------- scratch (no allocations allowed) ----------------
__device__ float g_qkv0[3][TOK * 192];   // Q,K,V for MHA0
__device__ float g_qkv1[3][TOK * 66];    // Q,K,V for MHA1
__device__ int   g_cIdx[2][4][1024];
__device__ int   g_cnt[2][4];
__device__ float g_c0[TOK * 192];
__device__ float g_c1[TOK * 66];

// ---------------- 128-thread mask compaction (runs inside gemm launch) ------
__device__ void compact_body(const int* __restrict__ m, int which, int b)
{
    int t = threadIdx.x;              // 128 threads, 8 elems each
    int base8 = t * 8;
    unsigned bits = 0;
#pragma unroll
    for (int i = 0; i < 8; i++)
        bits |= ((m[b * QLEN + base8 + i] != 0) ? 1u : 0u) << i;
    int pc = __popc(bits);

    int lane = t & 31, w = t >> 5;
    int pre = pc;
#pragma unroll
    for (int off = 1; off < 32; off <<= 1) {
        int nv = __shfl_up_sync(0xffffffffu, pre, off);
        if (lane >= off) pre += nv;
    }
    __shared__ int ws[4];
    if (lane == 31) ws[w] = pre;
    __syncthreads();
    int wbase = 0;
#pragma unroll
    for (int i = 0; i < 4; i++)
        if (i < w) wbase += ws[i];
    int ex = wbase + pre - pc;        // exclusive prefix for this thread
#pragma unroll
    for (int i = 0; i < 8; i++)
        if ((bits >> i) & 1)
            g_cIdx[which][b][ex++] = base8 + i;
    if (t == 0)
        g_cnt[which][b] = ws[0] + ws[1] + ws[2] + ws[3];
}

// ---------------- multi-job GEMM (cp.async 2-stage, 64x64 tile, 128 thr) ----
// Per-thread 4 rows x 8 cols (two 4-col runs), 16B SMEM loads for A and B.
struct GemmJob  { const float* A; const float* W; const float* B; float* C;
                  int N; int K; float scale; };
struct GemmJobs { GemmJob j[6]; const int* m0; const int* m1; };

__global__ __launch_bounds__(128) void gemm_cp(GemmJobs js)
{
    if (blockIdx.z == 6) {            // compaction slice (QKV launch only)
        if (blockIdx.x == 0 && blockIdx.y < 8) {
            int which = blockIdx.y >> 2, b = blockIdx.y & 3;
            compact_body(which ? js.m1 : js.m0, which, b);
        }
        return;
    }

    GemmJob jb = js.j[blockIdx.z];
    const int N = jb.N, K = jb.K;
    const int cBase = blockIdx.x * 64;
    if (cBase >= N) return;
    const int rBase = blockIdx.y * 64;
    const float* __restrict__ A    = jb.A;
    const float* __restrict__ W    = jb.W;
    const float* __restrict__ bias = jb.B;
    float* __restrict__ C          = jb.C;
    const float scale              = jb.scale;
    const bool aligned = ((K & 3) == 0) && ((N & 3) == 0);

    __shared__ __align__(16) float sA[2][64][36];   // [buf][row][k] (pad 36)
    __shared__ __align__(16) float sB[2][32][68];   // [buf][k][col] (pad 68)

    const int tt = threadIdx.x;
    const int tx = tt & 7;          // 8 col groups
    const int ty = tt >> 3;         // 16 row groups of 4

    uint32_t aB = (uint32_t)__cvta_generic_to_shared(&sA[0][0][0]);
    uint32_t bB = (uint32_t)__cvta_generic_to_shared(&sB[0][0][0]);

    // 16B-chunk fill: requires K%4==0 and N%4==0
    auto fill_vec = [&](int k0, int buf) {
#pragma unroll
        for (int i = 0; i < 4; i++) {       // A: 64 rows x 8 chunks
            int ci = tt + i * 128;
            int row = ci >> 3, kc = ci & 7;
            int kg = k0 + kc * 4;
            uint32_t dst = aB + ((buf * 64 + row) * 36 + kc * 4) * 4;
            const float* src = A + (size_t)(rBase + row) * K + kg;
            int bytes = min(max(K - kg, 0), 4) * 4;
            cpa16(dst, src, bytes);
        }
#pragma unroll
        for (int i = 0; i < 4; i++) {       // B: 32 k x 16 chunks
            int ci = tt + i * 128;
            int kr = ci >> 4, cc = ci & 15;
            int kg = k0 + kr;
            int cg = cBase + cc * 4;
            uint32_t dst = bB + ((buf * 32 + kr) * 68 + cc * 4) * 4;
            const float* src = W + (size_t)kg * N + cg;
            int bytes = (kg < K) ? min(max(N - cg, 0), 4) * 4 : 0;
            cpa16(dst, src, bytes);
        }
        cpa_commit();
    };
    // 4B-per-element fill: always aligned (float tensors)
    auto fill_sca = [&](int k0, int buf) {
#pragma unroll
        for (int i = 0; i < 16; i++) {      // A: 2048 elems
            int ci = tt + i * 128;
            int row = ci >> 5, kc = ci & 31;
            int kg = k0 + kc;
            uint32_t dst = aB + ((buf * 64 + row) * 36 + kc) * 4;
            const float* src = A + (size_t)(rBase + row) * K + kg;
            cpa4(dst, src, (kg < K) ? 4 : 0);
        }
#pragma unroll
        for (int i = 0; i < 16; i++) {      // B: 2048 elems
            int ci = tt + i * 128;
            int kr = ci >> 6, cc = ci & 63;
            int kg = k0 + kr;
            int cg = cBase + cc;
            uint32_t dst = bB + ((buf * 32 + kr) * 68 + cc) * 4;
            const float* src = W + (size_t)kg * N + cg;
            cpa4(dst, src, (kg < K && cg < N) ? 4 : 0);
        }
        cpa_commit();
    };
    auto fill = [&](int k0, int buf) {
        if (aligned) fill_vec(k0, buf); else fill_sca(k0, buf);
    };

    ull acc2[4][4];                 // [row][colpair]
#pragma unroll
    for (int r = 0; r < 4; r++)
#pragma unroll
        for (int j = 0; j < 4; j++) acc2[r][j] = 0ull;

    const int ntk = (K + 31) >> 5;
    fill(0, 0);
    for (int t = 0; t < ntk; t++) {
        cpa_waitall();
        __syncthreads();
        if (t + 1 < ntk) fill((t + 1) * 32, (t + 1) & 1);
        const int buf = t & 1;
#pragma unroll
        for (int g = 0; g < 8; g++) {       // 4 k per group
            float4 av[4];
#pragma unroll
            for (int r = 0; r < 4; r++)
                av[r] = *(const float4*)&sA[buf][ty * 4 + r][g * 4];
#pragma unroll
            for (int kk = 0; kk < 4; kk++) {
                ulonglong2 b0 = *(const ulonglong2*)&sB[buf][g * 4 + kk][4 * tx];
                ulonglong2 b1 = *(const ulonglong2*)&sB[buf][g * 4 + kk][4 * tx + 32];
                ull bp[4] = {b0.x, b0.y, b1.x, b1.y};
                ull ad[4];
#pragma unroll
                for (int r = 0; r < 4; r++) {
                    float a = (kk == 0) ? av[r].x : (kk == 1) ? av[r].y
                            : (kk == 2) ? av[r].z : av[r].w;
                    ad[r] = packf2(a, a);
                }
#pragma unroll
                for (int r = 0; r < 4; r++)
#pragma unroll
                    for (int j = 0; j < 4; j++)
                        acc2[r][j] = fma2(ad[r], bp[j], acc2[r][j]);
            }
        }
    }

#pragma unroll
    for (int r = 0; r < 4; r++) {
        int row = rBase + ty * 4 + r;
#pragma unroll
        for (int j = 0; j < 4; j++) {
            int cg = cBase + 4 * tx + (j >> 1) * 32 + (j & 1) * 2;
            if (cg + 1 < N) {
                float lo, hi;
                unpackf2(acc2[r][j], lo, hi);
                float2 o = make_float2((lo + bias[cg]) * scale,
                                       (hi + bias[cg + 1]) * scale);
                *(float2*)&C[(size_t)row * N + cg] = o;
            } else if (cg < N) {
                float lo, hi;
                unpackf2(acc2[r][j], lo, hi);
                C[(size_t)row * N + cg] = (lo + bias[cg]) * scale;
            }
        }
    }
}

// ---------------- attention inner tile (packed, no running max) -------------
template <int DPHP, int TQ, bool TAIL>
__device__ __forceinline__ void attn_tile(
    const float* __restrict__ sK, const float* __restrict__ sV,
    int kbase, int cnt,
    ull (&q2)[TQ][DPHP / 2], ull (&acc2)[TQ][DPHP / 2], float (&l)[TQ])
{
#pragma unroll 2
    for (int k = 0; k < 128; k++) {
        ull kr[DPHP / 2], vr[DPHP / 2];
        const ulonglong2* pk = (const ulonglong2*)(sK + k * DPHP);
        const ulonglong2* pv = (const ulonglong2*)(sV + k * DPHP);
#pragma unroll
        for (int i = 0; i < DPHP / 4; i++) {
            ulonglong2 a = pk[i]; kr[2 * i] = a.x; kr[2 * i + 1] = a.y;
            ulonglong2 b = pv[i]; vr[2 * i] = b.x; vr[2 * i + 1] = b.y;
        }
        float bias = 0.f;
        if (TAIL) bias = (kbase + k < cnt) ? 0.f : -1e30f;
        float p[TQ];
#pragma unroll
        for (int j = 0; j < TQ; j++) {
            ull d0 = mul2(q2[j][0], kr[0]);
            ull d1 = mul2(q2[j][1], kr[1]);
#pragma unroll
            for (int i = 2; i < DPHP / 2; i += 2) {
                d0 = fma2(q2[j][i],     kr[i],     d0);
                d1 = fma2(q2[j][i + 1], kr[i + 1], d1);
            }
            float lo, hi;
            unpackf2(add2(d0, d1), lo, hi);
            float dot = lo + hi;
            if (TAIL) dot += bias;
            p[j] = ex2(dot);
            l[j] += p[j];
        }
#pragma unroll
        for (int j = 0; j < TQ; j++) {
            ull pp = packf2(p[j], p[j]);
#pragma unroll
            for (int i = 0; i < DPHP / 2; i++)
                acc2[j][i] = fma2(pp, vr[i], acc2[j][i]);
        }
    }
}

// ---------------- flash attention (cp.async tile loads) ---------------------
template <int DPH, int DPHP, int TQ, int NH>
__device__ __forceinline__ void attn_body(
    int idx, const float* __restrict__ Q,
    const float* __restrict__ Ksrc, const float* __restrict__ Vsrc,
    const int* __restrict__ cIdx, const int* __restrict__ cntArr,
    float* __restrict__ C)
{
    constexpr int BH = 4 * NH;
    const int dim = NH * DPH;
    const int bh = idx % BH;
    const int qt = idx / BH;            // 4 query tiles of 256
    const int b = bh / NH, h = bh % NH;
    const int qi0 = (qt * 128 + threadIdx.x) * TQ;

    const int cnt = cntArr[b];
    const int nt = (cnt + 127) >> 7;

    __shared__ __align__(16) float sK[2][128 * DPHP];
    __shared__ __align__(16) float sV[2][128 * DPHP];

    uint32_t kB = (uint32_t)__cvta_generic_to_shared(&sK[0][0]);
    uint32_t vB = (uint32_t)__cvta_generic_to_shared(&sV[0][0]);

    const int kk = threadIdx.x;

    // pre-zero pad slots (DPH < DPHP): written once, never overwritten
    if constexpr (DPH != DPHP) {
#pragma unroll
        for (int bf = 0; bf < 2; bf++)
#pragma unroll
            for (int d = DPH; d < DPHP; d += 2) {
                *(float2*)&sK[bf][kk * DPHP + d] = make_float2(0.f, 0.f);
                *(float2*)&sV[bf][kk * DPHP + d] = make_float2(0.f, 0.f);
            }
    }

    auto afill = [&](int tile, int buf) {
        int j = tile * 128 + kk;
        int src = (j < cnt) ? cIdx[b * 1024 + j] : 0;
        const char* kp = (const char*)(Ksrc + (size_t)(b * QLEN + src) * dim + h * DPH);
        const char* vp = (const char*)(Vsrc + (size_t)(b * QLEN + src) * dim + h * DPH);
        uint32_t dk = kB + (buf * 128 + kk) * DPHP * 4;
        uint32_t dv = vB + (buf * 128 + kk) * DPHP * 4;
        if constexpr (DPH == 12) {
            // dim=192: row stride 768B, h*48B -> 16B-aligned
#pragma unroll
            for (int i = 0; i < 3; i++) {
                cpa16(dk + i * 16, kp + i * 16, 16);
                cpa16(dv + i * 16, vp + i * 16, 16);
            }
        } else {
            // dim=66: only 4B alignment guaranteed
#pragma unroll
            for (int i = 0; i < DPH; i++) {
                cpa4(dk + i * 4, kp + i * 4, 4);
                cpa4(dv + i * 4, vp + i * 4, 4);
            }
        }
        cpa_commit();
    };

    ull q2[TQ][DPHP / 2];
#pragma unroll
    for (int j = 0; j < TQ; j++) {
        const float* qp = Q + (size_t)(b * QLEN + qi0 + j) * dim + h * DPH;
        float qv[DPHP];
#pragma unroll
        for (int d = 0; d < DPH; d += 2) {
            float2 v2 = *(const float2*)(qp + d);
            qv[d] = v2.x; qv[d + 1] = v2.y;
        }
#pragma unroll
        for (int d = DPH; d < DPHP; d++) qv[d] = 0.f;
#pragma unroll
        for (int i = 0; i < DPHP / 2; i++)
            q2[j][i] = packf2(qv[2 * i], qv[2 * i + 1]);
    }

    float l[TQ];
    ull acc2[TQ][DPHP / 2];
#pragma unroll
    for (int j = 0; j < TQ; j++) {
        l[j] = 0.f;
#pragma unroll
        for (int i = 0; i < DPHP / 2; i++) acc2[j][i] = 0ull;
    }

    afill(0, 0);
    int cur = 0;
    for (int tt = 0; tt < nt; tt++) {
        cpa_waitall();
        __syncthreads();
        if (tt + 1 < nt) afill(tt + 1, cur ^ 1);
        if (tt == nt - 1)
            attn_tile<DPHP, TQ, true >(sK[cur], sV[cur], tt * 128, cnt, q2, acc2, l);
        else
            attn_tile<DPHP, TQ, false>(sK[cur], sV[cur], tt * 128, cnt, q2, acc2, l);
        cur ^= 1;
    }

    // normalize + direct write to context in (b, q, dim) layout
#pragma unroll
    for (int j = 0; j < TQ; j++) {
        float inv = 1.f / l[j];
        float* cp = C + (size_t)(b * QLEN + qi0 + j) * dim + h * DPH;
#pragma unroll
        for (int i = 0; i < DPH / 2; i++) {
            float lo, hi;
            unpackf2(acc2[j][i], lo, hi);
            *(float2*)(cp + 2 * i) = make_float2(lo * inv, hi * inv);
        }
    }
}

#define NB0 (64 * 4)    // 256
#define NB1 (44 * 4)    // 176

__global__ __launch_bounds__(128) void attn_both()
{
    int bx = blockIdx.x;
    if (bx < NB0)
        attn_body<12, 12, 2, 16>(bx, g_qkv0[0], g_qkv0[1], g_qkv0[2],
                                 &g_cIdx[0][0][0], &g_cnt[0][0], g_c0);
    else
        attn_body<6, 8, 2, 11>(bx - NB0, g_qkv1[0], g_qkv1[1], g_qkv1[2],
                               &g_cIdx[1][0][0], &g_cnt[1][0], g_c1);
}

// ---------------- launch ----------------------------------------------------
extern "C" void kernel_launch(void* const* d_in, const int* in_sizes, int n_in,
                              void* d_out, int out_size)
{
    const float* x     = (const float*)d_in[0];
    const float* y     = (const float*)d_in[1];
    const int*   mask0 = (const int*)d_in[2];
    const int*   mask1 = (const int*)d_in[3];
    const float* q0_w = (const float*)d_in[4],  *q0_b = (const float*)d_in[5];
    const float* k0_w = (const float*)d_in[6],  *k0_b = (const float*)d_in[7];
    const float* v0_w = (const float*)d_in[8],  *v0_b = (const float*)d_in[9];
    const float* o0_w = (const float*)d_in[10], *o0_b = (const float*)d_in[11];
    const float* q1_w = (const float*)d_in[12], *q1_b = (const float*)d_in[13];
    const float* k1_w = (const float*)d_in[14], *k1_b = (const float*)d_in[15];
    const float* v1_w = (const float*)d_in[16], *v1_b = (const float*)d_in[17];
    const float* o1_w = (const float*)d_in[18], *o1_b = (const float*)d_in[19];

    float* out0 = (float*)d_out;
    float* out1 = out0 + (size_t)TOK * 192;

    float *qkv0, *qkv1, *c0, *c1;
    cudaGetSymbolAddress((void**)&qkv0, g_qkv0);
    cudaGetSymbolAddress((void**)&qkv1, g_qkv1);
    cudaGetSymbolAddress((void**)&c0, g_c0);
    cudaGetSymbolAddress((void**)&c1, g_c1);

    const float LOG2E = 1.4426950408889634f;
    const float s0 = LOG2E / sqrtf(12.0f);
    const float s1 = LOG2E / sqrtf(6.0f);

    // fused QKV projections for both MHAs (6 jobs) + compaction slice (z=6)
    GemmJobs jq;
    jq.j[0] = { x, q0_w, q0_b, qkv0,                         192, 192, s0 };
    jq.j[1] = { x, k0_w, k0_b, qkv0 + (size_t)TOK * 192,     192, 192, 1.f };
    jq.j[2] = { x, v0_w, v0_b, qkv0 + (size_t)2 * TOK * 192, 192, 192, 1.f };
    jq.j[3] = { y, q1_w, q1_b, qkv1,                         66,  66,  s1 };
    jq.j[4] = { y, k1_w, k1_b, qkv1 + (size_t)TOK * 66,      66,  66,  1.f };
    jq.j[5] = { y, v1_w, v1_b, qkv1 + (size_t)2 * TOK * 66,  66,  66,  1.f };
    jq.m0 = mask0; jq.m1 = mask1;
    gemm_cp<<<dim3(3, 64, 7), 128>>>(jq);

    // fused attention (both MHAs), cp.async pipelined
    attn_both<<<NB0 + NB1, 128>>>();

    // fused output projections
    GemmJobs jo;
    jo.j[0] = { c0, o0_w, o0_b, out0, 192, 192, 1.f };
    jo.j[1] = { c1, o1_w, o1_b, out1, 66,  66,  1.f };
    jo.j[2] = jo.j[0]; jo.j[3] = jo.j[0]; jo.j[4] = jo.j[0]; jo.j[5] = jo.j[0];
    jo.m0 = mask0; jo.m1 = mask1;
    gemm_cp<<<dim3(3, 64, 2), 128>>>(jo);
}

// round 16
// speedup vs baseline: 1.0690x; 1.0555x over previous
#include <cuda_runtime.h>
#include <math.h>
#include <stdint.h>

#define TOK 4096            // 4 * 1024
#define QLEN 1024

typedef unsigned long long ull;

// ---------------- packed f32x2 helpers --------------------------------------
__device__ __forceinline__ ull fma2(ull a, ull b, ull c) {
    ull d; asm("fma.rn.f32x2 %0, %1, %2, %3;" : "=l"(d) : "l"(a), "l"(b), "l"(c));
    return d;
}
__device__ __forceinline__ ull mul2(ull a, ull b) {
    ull d; asm("mul.rn.f32x2 %0, %1, %2;" : "=l"(d) : "l"(a), "l"(b));
    return d;
}
__device__ __forceinline__ ull add2(ull a, ull b) {
    ull d; asm("add.rn.f32x2 %0, %1, %2;" : "=l"(d) : "l"(a), "l"(b));
    return d;
}
__device__ __forceinline__ ull packf2(float lo, float hi) {
    ull r; asm("mov.b64 %0, {%1, %2};" : "=l"(r) : "f"(lo), "f"(hi));
    return r;
}
__device__ __forceinline__ void unpackf2(ull v, float& lo, float& hi) {
    asm("mov.b64 {%0, %1}, %2;" : "=f"(lo), "=f"(hi) : "l"(v));
}
__device__ __forceinline__ float ex2(float x) {
    float y; asm("ex2.approx.ftz.f32 %0, %1;" : "=f"(y) : "f"(x));
    return y;
}

// ---------------- cp.async helpers ------------------------------------------
__device__ __forceinline__ void cpa16(uint32_t dst, const void* src, int bytes) {
    asm volatile("cp.async.cg.shared.global [%0], [%1], 16, %2;"
                 :: "r"(dst), "l"(src), "r"(bytes));
}
__device__ __forceinline__ void cpa8(uint32_t dst, const void* src, int bytes) {
    asm volatile("cp.async.ca.shared.global [%0], [%1], 8, %2;"
                 :: "r"(dst), "l"(src), "r"(bytes));
}
__device__ __forceinline__ void cpa_commit() {
    asm volatile("cp.async.commit_group;" ::: "memory");
}
__device__ __forceinline__ void cpa_waitall() {
    asm volatile("cp.async.wait_group 0;" ::: "memory");
}

// ---------------- scratch (no allocations allowed) ----------------
__device__ float g_qkv0[3][TOK * 192];   // Q,K,V for MHA0
__device__ float g_qkv1[3][TOK * 66];    // Q,K,V for MHA1
__device__ int   g_cIdx[2][4][1024];
__device__ int   g_cnt[2][4];
__device__ float g_c0[TOK * 192];
__device__ float g_c1[TOK * 66];

// ---------------- 128-thread mask compaction (runs inside gemm launch) ------
__device__ void compact_body(const int* __restrict__ m, int which, int b)
{
    int t = threadIdx.x;              // 128 threads, 8 elems each
    int base8 = t * 8;
    unsigned bits = 0;
#pragma unroll
    for (int i = 0; i < 8; i++)
        bits |= ((m[b * QLEN + base8 + i] != 0) ? 1u : 0u) << i;
    int pc = __popc(bits);

    int lane = t & 31, w = t >> 5;
    int pre = pc;
#pragma unroll
    for (int off = 1; off < 32; off <<= 1) {
        int nv = __shfl_up_sync(0xffffffffu, pre, off);
        if (lane >= off) pre += nv;
    }
    __shared__ int ws[4];
    if (lane == 31) ws[w] = pre;
    __syncthreads();
    int wbase = 0;
#pragma unroll
    for (int i = 0; i < 4; i++)
        if (i < w) wbase += ws[i];
    int ex = wbase + pre - pc;        // exclusive prefix for this thread
#pragma unroll
    for (int i = 0; i < 8; i++)
        if ((bits >> i) & 1)
            g_cIdx[which][b][ex++] = base8 + i;
    if (t == 0)
        g_cnt[which][b] = ws[0] + ws[1] + ws[2] + ws[3];
}

// ---------------- multi-job GEMM (cp.async 2-stage, 64x64 tile, 128 thr) ----
// Per-thread 4 rows x 8 cols (two 4-col runs), 16B SMEM loads for A and B.
// Dims here are always even, so the unaligned (non-16B) path can use 8B chunks:
// row strides like 66 floats = 264 B are 8B-aligned, as are even column offsets.
struct GemmJob  { const float* A; const float* W; const float* B; float* C;
                  int N; int K; float scale; };
struct GemmJobs { GemmJob j[6]; const int* m0; const int* m1; };

__global__ __launch_bounds__(128) void gemm_cp(GemmJobs js)
{
    if (blockIdx.z == 6) {            // compaction slice (QKV launch only)
        if (blockIdx.x == 0 && blockIdx.y < 8) {
            int which = blockIdx.y >> 2, b = blockIdx.y & 3;
            compact_body(which ? js.m1 : js.m0, which, b);
        }
        return;
    }

    GemmJob jb = js.j[blockIdx.z];
    const int N = jb.N, K = jb.K;
    const int cBase = blockIdx.x * 64;
    if (cBase >= N) return;
    const int rBase = blockIdx.y * 64;
    const float* __restrict__ A    = jb.A;
    const float* __restrict__ W    = jb.W;
    const float* __restrict__ bias = jb.B;
    float* __restrict__ C          = jb.C;
    const float scale              = jb.scale;
    const bool aligned = ((K & 3) == 0) && ((N & 3) == 0);

    __shared__ __align__(16) float sA[2][64][36];   // [buf][row][k] (pad 36)
    __shared__ __align__(16) float sB[2][32][68];   // [buf][k][col] (pad 68)

    const int tt = threadIdx.x;
    const int tx = tt & 7;          // 8 col groups
    const int ty = tt >> 3;         // 16 row groups of 4

    uint32_t aB = (uint32_t)__cvta_generic_to_shared(&sA[0][0][0]);
    uint32_t bB = (uint32_t)__cvta_generic_to_shared(&sB[0][0][0]);

    // 16B-chunk fill: requires K%4==0 and N%4==0
    auto fill_vec = [&](int k0, int buf) {
#pragma unroll
        for (int i = 0; i < 4; i++) {       // A: 64 rows x 8 chunks
            int ci = tt + i * 128;
            int row = ci >> 3, kc = ci & 7;
            int kg = k0 + kc * 4;
            uint32_t dst = aB + ((buf * 64 + row) * 36 + kc * 4) * 4;
            const float* src = A + (size_t)(rBase + row) * K + kg;
            int bytes = min(max(K - kg, 0), 4) * 4;
            cpa16(dst, src, bytes);
        }
#pragma unroll
        for (int i = 0; i < 4; i++) {       // B: 32 k x 16 chunks
            int ci = tt + i * 128;
            int kr = ci >> 4, cc = ci & 15;
            int kg = k0 + kr;
            int cg = cBase + cc * 4;
            uint32_t dst = bB + ((buf * 32 + kr) * 68 + cc * 4) * 4;
            const float* src = W + (size_t)kg * N + cg;
            int bytes = (kg < K) ? min(max(N - cg, 0), 4) * 4 : 0;
            cpa16(dst, src, bytes);
        }
        cpa_commit();
    };
    // 8B-pair fill: requires only even K and N (true for 66-dim tensors)
    auto fill_pair = [&](int k0, int buf) {
#pragma unroll
        for (int i = 0; i < 8; i++) {       // A: 64 rows x 16 pairs = 1024
            int p = tt + i * 128;
            int row = p >> 4, pc = p & 15;
            int kg = k0 + pc * 2;
            uint32_t dst = aB + ((buf * 64 + row) * 36 + pc * 2) * 4;
            const float* src = A + (size_t)(rBase + row) * K + kg;
            int bytes = (kg < K) ? ((kg + 1 < K) ? 8 : 4) : 0;
            cpa8(dst, src, bytes);
        }
#pragma unroll
        for (int i = 0; i < 8; i++) {       // B: 32 k x 32 pairs = 1024
            int p = tt + i * 128;
            int kr = p >> 5, pcc = p & 31;
            int kg = k0 + kr;
            int cg = cBase + pcc * 2;
            uint32_t dst = bB + ((buf * 32 + kr) * 68 + pcc * 2) * 4;
            const float* src = W + (size_t)kg * N + cg;
            int bytes = (kg < K && cg < N) ? ((cg + 1 < N) ? 8 : 4) : 0;
            cpa8(dst, src, bytes);
        }
        cpa_commit();
    };
    auto fill = [&](int k0, int buf) {
        if (aligned) fill_vec(k0, buf); else fill_pair(k0, buf);
    };

    ull acc2[4][4];                 // [row][colpair]
#pragma unroll
    for (int r = 0; r < 4; r++)
#pragma unroll
        for (int j = 0; j < 4; j++) acc2[r][j] = 0ull;

    const int ntk = (K + 31) >> 5;
    const int gtail = ((K - (ntk - 1) * 32) + 3) >> 2;   // groups in last tile

    fill(0, 0);
    for (int t = 0; t < ntk; t++) {
        cpa_waitall();
        __syncthreads();
        if (t + 1 < ntk) fill((t + 1) * 32, (t + 1) & 1);
        const int buf = t & 1;

        auto body = [&](int g) {
            float4 av[4];
#pragma unroll
            for (int r = 0; r < 4; r++)
                av[r] = *(const float4*)&sA[buf][ty * 4 + r][g * 4];
#pragma unroll
            for (int kk = 0; kk < 4; kk++) {
                ulonglong2 b0 = *(const ulonglong2*)&sB[buf][g * 4 + kk][4 * tx];
                ulonglong2 b1 = *(const ulonglong2*)&sB[buf][g * 4 + kk][4 * tx + 32];
                ull bp[4] = {b0.x, b0.y, b1.x, b1.y};
                ull ad[4];
#pragma unroll
                for (int r = 0; r < 4; r++) {
                    float a = (kk == 0) ? av[r].x : (kk == 1) ? av[r].y
                            : (kk == 2) ? av[r].z : av[r].w;
                    ad[r] = packf2(a, a);
                }
#pragma unroll
                for (int r = 0; r < 4; r++)
#pragma unroll
                    for (int j = 0; j < 4; j++)
                        acc2[r][j] = fma2(ad[r], bp[j], acc2[r][j]);
            }
        };

        if (t + 1 < ntk || gtail == 8) {
#pragma unroll
            for (int g = 0; g < 8; g++) body(g);
        } else {
            for (int g = 0; g < gtail; g++) body(g);   // small-K tail tile
        }
    }

#pragma unroll
    for (int r = 0; r < 4; r++) {
        int row = rBase + ty * 4 + r;
#pragma unroll
        for (int j = 0; j < 4; j++) {
            int cg = cBase + 4 * tx + (j >> 1) * 32 + (j & 1) * 2;
            if (cg + 1 < N) {
                float lo, hi;
                unpackf2(acc2[r][j], lo, hi);
                float2 o = make_float2((lo + bias[cg]) * scale,
                                       (hi + bias[cg + 1]) * scale);
                *(float2*)&C[(size_t)row * N + cg] = o;
            } else if (cg < N) {
                float lo, hi;
                unpackf2(acc2[r][j], lo, hi);
                C[(size_t)row * N + cg] = (lo + bias[cg]) * scale;
            }
        }
    }
}

// ---------------- attention inner tile (packed, no running max) -------------
template <int DPHP, int TQ, bool TAIL>
__device__ __forceinline__ void attn_tile(
    const float* __restrict__ sK, const float* __restrict__ sV,
    int kbase, int cnt,
    ull (&q2)[TQ][DPHP / 2], ull (&acc2)[TQ][DPHP / 2], float (&l)[TQ])
{
#pragma unroll 2
    for (int k = 0; k < 128; k++) {
        ull kr[DPHP / 2], vr[DPHP / 2];
        const ulonglong2* pk = (const ulonglong2*)(sK + k * DPHP);
        const ulonglong2* pv = (const ulonglong2*)(sV + k * DPHP);
#pragma unroll
        for (int i = 0; i < DPHP / 4; i++) {
            ulonglong2 a = pk[i]; kr[2 * i] = a.x; kr[2 * i + 1] = a.y;
            ulonglong2 b = pv[i]; vr[2 * i] = b.x; vr[2 * i + 1] = b.y;
        }
        float bias = 0.f;
        if (TAIL) bias = (kbase + k < cnt) ? 0.f : -1e30f;
        float p[TQ];
#pragma unroll
        for (int j = 0; j < TQ; j++) {
            ull d0 = mul2(q2[j][0], kr[0]);
            ull d1 = mul2(q2[j][1], kr[1]);
#pragma unroll
            for (int i = 2; i < DPHP / 2; i += 2) {
                d0 = fma2(q2[j][i],     kr[i],     d0);
                d1 = fma2(q2[j][i + 1], kr[i + 1], d1);
            }
            float lo, hi;
            unpackf2(add2(d0, d1), lo, hi);
            float dot = lo + hi;
            if (TAIL) dot += bias;
            p[j] = ex2(dot);
            l[j] += p[j];
        }
#pragma unroll
        for (int j = 0; j < TQ; j++) {
            ull pp = packf2(p[j], p[j]);
#pragma unroll
            for (int i = 0; i < DPHP / 2; i++)
                acc2[j][i] = fma2(pp, vr[i], acc2[j][i]);
        }
    }
}

// ---------------- flash attention (cp.async tile loads) ---------------------
template <int DPH, int DPHP, int TQ, int NH>
__device__ __forceinline__ void attn_body(
    int idx, const float* __restrict__ Q,
    const float* __restrict__ Ksrc, const float* __restrict__ Vsrc,
    const int* __restrict__ cIdx, const int* __restrict__ cntArr,
    float* __restrict__ C)
{
    constexpr int BH = 4 * NH;
    const int dim = NH * DPH;
    const int bh = idx % BH;
    const int qt = idx / BH;            // 4 query tiles of 256
    const int b = bh / NH, h = bh % NH;
    const int qi0 = (qt * 128 + threadIdx.x) * TQ;

    const int cnt = cntArr[b];
    const int nt = (cnt + 127) >> 7;

    __shared__ __align__(16) float sK[2][128 * DPHP];
    __shared__ __align__(16) float sV[2][128 * DPHP];

    uint32_t kB = (uint32_t)__cvta_generic_to_shared(&sK[0][0]);
    uint32_t vB = (uint32_t)__cvta_generic_to_shared(&sV[0][0]);

    const int kk = threadIdx.x;

    // pre-zero pad slots (DPH < DPHP): written once, never overwritten
    if constexpr (DPH != DPHP) {
#pragma unroll
        for (int bf = 0; bf < 2; bf++)
#pragma unroll
            for (int d = DPH; d < DPHP; d += 2) {
                *(float2*)&sK[bf][kk * DPHP + d] = make_float2(0.f, 0.f);
                *(float2*)&sV[bf][kk * DPHP + d] = make_float2(0.f, 0.f);
            }
    }

    auto afill = [&](int tile, int buf) {
        int j = tile * 128 + kk;
        int src = (j < cnt) ? cIdx[b * 1024 + j] : 0;
        const char* kp = (const char*)(Ksrc + (size_t)(b * QLEN + src) * dim + h * DPH);
        const char* vp = (const char*)(Vsrc + (size_t)(b * QLEN + src) * dim + h * DPH);
        uint32_t dk = kB + (buf * 128 + kk) * DPHP * 4;
        uint32_t dv = vB + (buf * 128 + kk) * DPHP * 4;
        if constexpr (DPH == 12) {
            // dim=192: row stride 768B, h*48B -> 16B-aligned
#pragma unroll
            for (int i = 0; i < 3; i++) {
                cpa16(dk + i * 16, kp + i * 16, 16);
                cpa16(dv + i * 16, vp + i * 16, 16);
            }
        } else {
            // dim=66: row stride 264B, h*24B -> 8B-aligned everywhere
#pragma unroll
            for (int i = 0; i < 3; i++) {
                cpa8(dk + i * 8, kp + i * 8, 8);
                cpa8(dv + i * 8, vp + i * 8, 8);
            }
        }
        cpa_commit();
    };

    ull q2[TQ][DPHP / 2];
#pragma unroll
    for (int j = 0; j < TQ; j++) {
        const float* qp = Q + (size_t)(b * QLEN + qi0 + j) * dim + h * DPH;
        float qv[DPHP];
#pragma unroll
        for (int d = 0; d < DPH; d += 2) {
            float2 v2 = *(const float2*)(qp + d);
            qv[d] = v2.x; qv[d + 1] = v2.y;
        }
#pragma unroll
        for (int d = DPH; d < DPHP; d++) qv[d] = 0.f;
#pragma unroll
        for (int i = 0; i < DPHP / 2; i++)
            q2[j][i] = packf2(qv[2 * i], qv[2 * i + 1]);
    }

    float l[TQ];
    ull acc2[TQ][DPHP / 2];
#pragma unroll
    for (int j = 0; j < TQ; j++) {
        l[j] = 0.f;
#pragma unroll
        for (int i = 0; i < DPHP / 2; i++) acc2[j][i] = 0ull;
    }

    afill(0, 0);
    int cur = 0;
    for (int tt = 0; tt < nt; tt++) {
        cpa_waitall();
        __syncthreads();
        if (tt + 1 < nt) afill(tt + 1, cur ^ 1);
        if (tt == nt - 1)
            attn_tile<DPHP, TQ, true >(sK[cur], sV[cur], tt * 128, cnt, q2, acc2, l);
        else
            attn_tile<DPHP, TQ, false>(sK[cur], sV[cur], tt * 128, cnt, q2, acc2, l);
        cur ^= 1;
    }

    // normalize + direct write to context in (b, q, dim) layout
#pragma unroll
    for (int j = 0; j < TQ; j++) {
        float inv = 1.f / l[j];
        float* cp = C + (size_t)(b * QLEN + qi0 + j) * dim + h * DPH;
#pragma unroll
        for (int i = 0; i < DPH / 2; i++) {
            float lo, hi;
            unpackf2(acc2[j][i], lo, hi);
            *(float2*)(cp + 2 * i) = make_float2(lo * inv, hi * inv);
        }
    }
}

#define NB0 (64 * 4)    // 256
#define NB1 (44 * 4)    // 176

__global__ __launch_bounds__(128) void attn_both()
{
    int bx = blockIdx.x;
    if (bx < NB0)
        attn_body<12, 12, 2, 16>(bx, g_qkv0[0], g_qkv0[1], g_qkv0[2],
                                 &g_cIdx[0][0][0], &g_cnt[0][0], g_c0);
    else
        attn_body<6, 8, 2, 11>(bx - NB0, g_qkv1[0], g_qkv1[1], g_qkv1[2],
                               &g_cIdx[1][0][0], &g_cnt[1][0], g_c1);
}

// ---------------- launch ----------------------------------------------------
extern "C" void kernel_launch(void* const* d_in, const int* in_sizes, int n_in,
                              void* d_out, int out_size)
{
    const float* x     = (const float*)d_in[0];
    const float* y     = (const float*)d_in[1];
    const int*   mask0 = (const int*)d_in[2];
    const int*   mask1 = (const int*)d_in[3];
    const float* q0_w = (const float*)d_in[4],  *q0_b = (const float*)d_in[5];
    const float* k0_w = (const float*)d_in[6],  *k0_b = (const float*)d_in[7];
    const float* v0_w = (const float*)d_in[8],  *v0_b = (const float*)d_in[9];
    const float* o0_w = (const float*)d_in[10], *o0_b = (const float*)d_in[11];
    const float* q1_w = (const float*)d_in[12], *q1_b = (const float*)d_in[13];
    const float* k1_w = (const float*)d_in[14], *k1_b = (const float*)d_in[15];
    const float* v1_w = (const float*)d_in[16], *v1_b = (const float*)d_in[17];
    const float* o1_w = (const float*)d_in[18], *o1_b = (const float*)d_in[19];

    float* out0 = (float*)d_out;
    float* out1 = out0 + (size_t)TOK * 192;

    float *qkv0, *qkv1, *c0, *c1;
    cudaGetSymbolAddress((void**)&qkv0, g_qkv0);
    cudaGetSymbolAddress((void**)&qkv1, g_qkv1);
    cudaGetSymbolAddress((void**)&c0, g_c0);
    cudaGetSymbolAddress((void**)&c1, g_c1);

    const float LOG2E = 1.4426950408889634f;
    const float s0 = LOG2E / sqrtf(12.0f);
    const float s1 = LOG2E / sqrtf(6.0f);

    // fused QKV projections for both MHAs (6 jobs) + compaction slice (z=6)
    GemmJobs jq;
    jq.j[0] = { x, q0_w, q0_b, qkv0,                         192, 192, s0 };
    jq.j[1] = { x, k0_w, k0_b, qkv0 + (size_t)TOK * 192,     192, 192, 1.f };
    jq.j[2] = { x, v0_w, v0_b, qkv0 + (size_t)2 * TOK * 192, 192, 192, 1.f };
    jq.j[3] = { y, q1_w, q1_b, qkv1,                         66,  66,  s1 };
    jq.j[4] = { y, k1_w, k1_b, qkv1 + (size_t)TOK * 66,      66,  66,  1.f };
    jq.j[5] = { y, v1_w, v1_b, qkv1 + (size_t)2 * TOK * 66,  66,  66,  1.f };
    jq.m0 = mask0; jq.m1 = mask1;
    gemm_cp<<<dim3(3, 64, 7), 128>>>(jq);

    // fused attention (both MHAs), cp.async pipelined
    attn_both<<<NB0 + NB1, 128>>>();

    // fused output projections
    GemmJobs jo;
    jo.j[0] = { c0, o0_w, o0_b, out0, 192, 192, 1.f };
    jo.j[1] = { c1, o1_w, o1_b, out1, 66,  66,  1.f };
    jo.j[2] = jo.j[0]; jo.j[3] = jo.j[0]; jo.j[4] = jo.j[0]; jo.j[5] = jo.j[0];
    jo.m0 = mask0; jo.m1 = mask1;
    gemm_cp<<<dim3(3, 64, 2), 128>>>(jo);
}

// round 17
// speedup vs baseline: 1.1692x; 1.0937x over previous
#include <cuda_runtime.h>
#include <math.h>
#include <stdint.h>

#define TOK 4096            // 4 * 1024
#define QLEN 1024

typedef unsigned long long ull;

// ---------------- packed f32x2 helpers --------------------------------------
__device__ __forceinline__ ull fma2(ull a, ull b, ull c) {
    ull d; asm("fma.rn.f32x2 %0, %1, %2, %3;" : "=l"(d) : "l"(a), "l"(b), "l"(c));
    return d;
}
__device__ __forceinline__ ull mul2(ull a, ull b) {
    ull d; asm("mul.rn.f32x2 %0, %1, %2;" : "=l"(d) : "l"(a), "l"(b));
    return d;
}
__device__ __forceinline__ ull add2(ull a, ull b) {
    ull d; asm("add.rn.f32x2 %0, %1, %2;" : "=l"(d) : "l"(a), "l"(b));
    return d;
}
__device__ __forceinline__ ull packf2(float lo, float hi) {
    ull r; asm("mov.b64 %0, {%1, %2};" : "=l"(r) : "f"(lo), "f"(hi));
    return r;
}
__device__ __forceinline__ void unpackf2(ull v, float& lo, float& hi) {
    asm("mov.b64 {%0, %1}, %2;" : "=f"(lo), "=f"(hi) : "l"(v));
}
__device__ __forceinline__ float ex2(float x) {
    float y; asm("ex2.approx.ftz.f32 %0, %1;" : "=f"(y) : "f"(x));
    return y;
}

// ---------------- cp.async helpers ------------------------------------------
__device__ __forceinline__ void cpa16(uint32_t dst, const void* src, int bytes) {
    asm volatile("cp.async.cg.shared.global [%0], [%1], 16, %2;"
                 :: "r"(dst), "l"(src), "r"(bytes));
}
__device__ __forceinline__ void cpa8(uint32_t dst, const void* src, int bytes) {
    asm volatile("cp.async.ca.shared.global [%0], [%1], 8, %2;"
                 :: "r"(dst), "l"(src), "r"(bytes));
}
__device__ __forceinline__ void cpa_commit() {
    asm volatile("cp.async.commit_group;" ::: "memory");
}
__device__ __forceinline__ void cpa_waitall() {
    asm volatile("cp.async.wait_group 0;" ::: "memory");
}

// ---------------- scratch (no allocations allowed) ----------------
__device__ float g_qkv0[3][TOK * 192];   // Q,K,V for MHA0
__device__ float g_qkv1[3][TOK * 66];    // Q,K,V for MHA1
__device__ int   g_cIdx[2][4][1024];
__device__ int   g_cnt[2][4];
__device__ float g_c0[TOK * 192];
__device__ float g_c1[TOK * 66];

// ---------------- 128-thread mask compaction (runs inside gemm launch) ------
__device__ void compact_body(const int* __restrict__ m, int which, int b)
{
    int t = threadIdx.x;              // 128 threads, 8 elems each
    int base8 = t * 8;
    unsigned bits = 0;
#pragma unroll
    for (int i = 0; i < 8; i++)
        bits |= ((m[b * QLEN + base8 + i] != 0) ? 1u : 0u) << i;
    int pc = __popc(bits);

    int lane = t & 31, w = t >> 5;
    int pre = pc;
#pragma unroll
    for (int off = 1; off < 32; off <<= 1) {
        int nv = __shfl_up_sync(0xffffffffu, pre, off);
        if (lane >= off) pre += nv;
    }
    __shared__ int ws[4];
    if (lane == 31) ws[w] = pre;
    __syncthreads();
    int wbase = 0;
#pragma unroll
    for (int i = 0; i < 4; i++)
        if (i < w) wbase += ws[i];
    int ex = wbase + pre - pc;        // exclusive prefix for this thread
#pragma unroll
    for (int i = 0; i < 8; i++)
        if ((bits >> i) & 1)
            g_cIdx[which][b][ex++] = base8 + i;
    if (t == 0)
        g_cnt[which][b] = ws[0] + ws[1] + ws[2] + ws[3];
}

// ---------------- multi-job GEMM (cp.async 2-stage, 64x64 tile, 128 thr) ----
struct GemmJob  { const float* A; const float* W; const float* B; float* C;
                  int N; int K; float scale; };
struct GemmJobs { GemmJob j[6]; const int* m0; const int* m1; };

__global__ __launch_bounds__(128) void gemm_cp(GemmJobs js)
{
    if (blockIdx.z == 6) {            // compaction slice (QKV launch only)
        if (blockIdx.x == 0 && blockIdx.y < 8) {
            int which = blockIdx.y >> 2, b = blockIdx.y & 3;
            compact_body(which ? js.m1 : js.m0, which, b);
        }
        return;
    }

    GemmJob jb = js.j[blockIdx.z];
    const int N = jb.N, K = jb.K;
    const int cBase = blockIdx.x * 64;
    if (cBase >= N) return;
    const int rBase = blockIdx.y * 64;
    const float* __restrict__ A    = jb.A;
    const float* __restrict__ W    = jb.W;
    const float* __restrict__ bias = jb.B;
    float* __restrict__ C          = jb.C;
    const float scale              = jb.scale;
    const bool aligned = ((K & 3) == 0) && ((N & 3) == 0);

    __shared__ __align__(16) float sA[2][64][36];   // [buf][row][k] (pad 36)
    __shared__ __align__(16) float sB[2][32][68];   // [buf][k][col] (pad 68)

    const int tt = threadIdx.x;
    const int tx = tt & 7;          // 8 col groups
    const int ty = tt >> 3;         // 16 row groups of 4

    uint32_t aB = (uint32_t)__cvta_generic_to_shared(&sA[0][0][0]);
    uint32_t bB = (uint32_t)__cvta_generic_to_shared(&sB[0][0][0]);

    auto fill_vec = [&](int k0, int buf) {
#pragma unroll
        for (int i = 0; i < 4; i++) {       // A: 64 rows x 8 chunks
            int ci = tt + i * 128;
            int row = ci >> 3, kc = ci & 7;
            int kg = k0 + kc * 4;
            uint32_t dst = aB + ((buf * 64 + row) * 36 + kc * 4) * 4;
            const float* src = A + (size_t)(rBase + row) * K + kg;
            int bytes = min(max(K - kg, 0), 4) * 4;
            cpa16(dst, src, bytes);
        }
#pragma unroll
        for (int i = 0; i < 4; i++) {       // B: 32 k x 16 chunks
            int ci = tt + i * 128;
            int kr = ci >> 4, cc = ci & 15;
            int kg = k0 + kr;
            int cg = cBase + cc * 4;
            uint32_t dst = bB + ((buf * 32 + kr) * 68 + cc * 4) * 4;
            const float* src = W + (size_t)kg * N + cg;
            int bytes = (kg < K) ? min(max(N - cg, 0), 4) * 4 : 0;
            cpa16(dst, src, bytes);
        }
        cpa_commit();
    };
    auto fill_pair = [&](int k0, int buf) {
#pragma unroll
        for (int i = 0; i < 8; i++) {       // A: 64 rows x 16 pairs = 1024
            int p = tt + i * 128;
            int row = p >> 4, pc = p & 15;
            int kg = k0 + pc * 2;
            uint32_t dst = aB + ((buf * 64 + row) * 36 + pc * 2) * 4;
            const float* src = A + (size_t)(rBase + row) * K + kg;
            int bytes = (kg < K) ? ((kg + 1 < K) ? 8 : 4) : 0;
            cpa8(dst, src, bytes);
        }
#pragma unroll
        for (int i = 0; i < 8; i++) {       // B: 32 k x 32 pairs = 1024
            int p = tt + i * 128;
            int kr = p >> 5, pcc = p & 31;
            int kg = k0 + kr;
            int cg = cBase + pcc * 2;
            uint32_t dst = bB + ((buf * 32 + kr) * 68 + pcc * 2) * 4;
            const float* src = W + (size_t)kg * N + cg;
            int bytes = (kg < K && cg < N) ? ((cg + 1 < N) ? 8 : 4) : 0;
            cpa8(dst, src, bytes);
        }
        cpa_commit();
    };
    auto fill = [&](int k0, int buf) {
        if (aligned) fill_vec(k0, buf); else fill_pair(k0, buf);
    };

    ull acc2[4][4];                 // [row][colpair]
#pragma unroll
    for (int r = 0; r < 4; r++)
#pragma unroll
        for (int j = 0; j < 4; j++) acc2[r][j] = 0ull;

    const int ntk = (K + 31) >> 5;
    const int gtail = ((K - (ntk - 1) * 32) + 3) >> 2;   // groups in last tile

    fill(0, 0);
    for (int t = 0; t < ntk; t++) {
        cpa_waitall();
        __syncthreads();
        if (t + 1 < ntk) fill((t + 1) * 32, (t + 1) & 1);
        const int buf = t & 1;

        auto body = [&](int g) {
            float4 av[4];
#pragma unroll
            for (int r = 0; r < 4; r++)
                av[r] = *(const float4*)&sA[buf][ty * 4 + r][g * 4];
#pragma unroll
            for (int kk = 0; kk < 4; kk++) {
                ulonglong2 b0 = *(const ulonglong2*)&sB[buf][g * 4 + kk][4 * tx];
                ulonglong2 b1 = *(const ulonglong2*)&sB[buf][g * 4 + kk][4 * tx + 32];
                ull bp[4] = {b0.x, b0.y, b1.x, b1.y};
                ull ad[4];
#pragma unroll
                for (int r = 0; r < 4; r++) {
                    float a = (kk == 0) ? av[r].x : (kk == 1) ? av[r].y
                            : (kk == 2) ? av[r].z : av[r].w;
                    ad[r] = packf2(a, a);
                }
#pragma unroll
                for (int r = 0; r < 4; r++)
#pragma unroll
                    for (int j = 0; j < 4; j++)
                        acc2[r][j] = fma2(ad[r], bp[j], acc2[r][j]);
            }
        };

        if (t + 1 < ntk || gtail == 8) {
#pragma unroll
            for (int g = 0; g < 8; g++) body(g);
        } else {
            for (int g = 0; g < gtail; g++) body(g);   // small-K tail tile
        }
    }

#pragma unroll
    for (int r = 0; r < 4; r++) {
        int row = rBase + ty * 4 + r;
#pragma unroll
        for (int j = 0; j < 4; j++) {
            int cg = cBase + 4 * tx + (j >> 1) * 32 + (j & 1) * 2;
            if (cg + 1 < N) {
                float lo, hi;
                unpackf2(acc2[r][j], lo, hi);
                float2 o = make_float2((lo + bias[cg]) * scale,
                                       (hi + bias[cg + 1]) * scale);
                *(float2*)&C[(size_t)row * N + cg] = o;
            } else if (cg < N) {
                float lo, hi;
                unpackf2(acc2[r][j], lo, hi);
                C[(size_t)row * N + cg] = (lo + bias[cg]) * scale;
            }
        }
    }
}

// ---------------- attention inner tile (packed, no max, no bias) ------------
// FULL: compile-time 128 keys, unrolled. Tail: dynamic kend (pad keys never
// processed — compaction guarantees all processed keys are unmasked).
template <int DPHP, int TQ, bool FULL>
__device__ __forceinline__ void attn_tile(
    const float* __restrict__ sK, const float* __restrict__ sV,
    int kend,
    ull (&q2)[TQ][DPHP / 2], ull (&acc2)[TQ][DPHP / 2], float (&l)[TQ])
{
    const int ke = FULL ? 128 : kend;
#pragma unroll 2
    for (int k = 0; k < ke; k++) {
        ull kr[DPHP / 2], vr[DPHP / 2];
        const ulonglong2* pk = (const ulonglong2*)(sK + k * DPHP);
        const ulonglong2* pv = (const ulonglong2*)(sV + k * DPHP);
#pragma unroll
        for (int i = 0; i < DPHP / 4; i++) {
            ulonglong2 a = pk[i]; kr[2 * i] = a.x; kr[2 * i + 1] = a.y;
            ulonglong2 b = pv[i]; vr[2 * i] = b.x; vr[2 * i + 1] = b.y;
        }
        float p[TQ];
#pragma unroll
        for (int j = 0; j < TQ; j++) {
            ull d0 = mul2(q2[j][0], kr[0]);
            ull d1 = mul2(q2[j][1], kr[1]);
#pragma unroll
            for (int i = 2; i < DPHP / 2; i += 2) {
                d0 = fma2(q2[j][i],     kr[i],     d0);
                d1 = fma2(q2[j][i + 1], kr[i + 1], d1);
            }
            float lo, hi;
            unpackf2(add2(d0, d1), lo, hi);
            p[j] = ex2(lo + hi);
            l[j] += p[j];
        }
#pragma unroll
        for (int j = 0; j < TQ; j++) {
            ull pp = packf2(p[j], p[j]);
#pragma unroll
            for (int i = 0; i < DPHP / 2; i++)
                acc2[j][i] = fma2(pp, vr[i], acc2[j][i]);
        }
    }
}

// ---------------- flash attention (cp.async tile loads) ---------------------
template <int DPH, int DPHP, int TQ, int NH>
__device__ __forceinline__ void attn_body(
    int idx, const float* __restrict__ Q,
    const float* __restrict__ Ksrc, const float* __restrict__ Vsrc,
    const int* __restrict__ cIdx, const int* __restrict__ cntArr,
    float* __restrict__ C)
{
    constexpr int BH = 4 * NH;
    const int dim = NH * DPH;
    const int bh = idx % BH;
    const int qt = idx / BH;            // 4 query tiles of 256
    const int b = bh / NH, h = bh % NH;
    const int qi0 = (qt * 128 + threadIdx.x) * TQ;

    const int cnt = cntArr[b];
    const int nt = (cnt + 127) >> 7;

    __shared__ __align__(16) float sK[2][128 * DPHP];
    __shared__ __align__(16) float sV[2][128 * DPHP];

    uint32_t kB = (uint32_t)__cvta_generic_to_shared(&sK[0][0]);
    uint32_t vB = (uint32_t)__cvta_generic_to_shared(&sV[0][0]);

    const int kk = threadIdx.x;

    // pre-zero pad slots (DPH < DPHP): written once, never overwritten
    if constexpr (DPH != DPHP) {
#pragma unroll
        for (int bf = 0; bf < 2; bf++)
#pragma unroll
            for (int d = DPH; d < DPHP; d += 2) {
                *(float2*)&sK[bf][kk * DPHP + d] = make_float2(0.f, 0.f);
                *(float2*)&sV[bf][kk * DPHP + d] = make_float2(0.f, 0.f);
            }
    }

    auto afill = [&](int tile, int buf) {
        int j = tile * 128 + kk;
        int src = (j < cnt) ? cIdx[b * 1024 + j] : 0;
        const char* kp = (const char*)(Ksrc + (size_t)(b * QLEN + src) * dim + h * DPH);
        const char* vp = (const char*)(Vsrc + (size_t)(b * QLEN + src) * dim + h * DPH);
        uint32_t dk = kB + (buf * 128 + kk) * DPHP * 4;
        uint32_t dv = vB + (buf * 128 + kk) * DPHP * 4;
        if constexpr (DPH == 12) {
            // dim=192: row stride 768B, h*48B -> 16B-aligned
#pragma unroll
            for (int i = 0; i < 3; i++) {
                cpa16(dk + i * 16, kp + i * 16, 16);
                cpa16(dv + i * 16, vp + i * 16, 16);
            }
        } else {
            // dim=66: row stride 264B, h*24B -> 8B-aligned everywhere
#pragma unroll
            for (int i = 0; i < 3; i++) {
                cpa8(dk + i * 8, kp + i * 8, 8);
                cpa8(dv + i * 8, vp + i * 8, 8);
            }
        }
        cpa_commit();
    };

    ull q2[TQ][DPHP / 2];
#pragma unroll
    for (int j = 0; j < TQ; j++) {
        const float* qp = Q + (size_t)(b * QLEN + qi0 + j) * dim + h * DPH;
        float qv[DPHP];
#pragma unroll
        for (int d = 0; d < DPH; d += 2) {
            float2 v2 = *(const float2*)(qp + d);
            qv[d] = v2.x; qv[d + 1] = v2.y;
        }
#pragma unroll
        for (int d = DPH; d < DPHP; d++) qv[d] = 0.f;
#pragma unroll
        for (int i = 0; i < DPHP / 2; i++)
            q2[j][i] = packf2(qv[2 * i], qv[2 * i + 1]);
    }

    float l[TQ];
    ull acc2[TQ][DPHP / 2];
#pragma unroll
    for (int j = 0; j < TQ; j++) {
        l[j] = 0.f;
#pragma unroll
        for (int i = 0; i < DPHP / 2; i++) acc2[j][i] = 0ull;
    }

    afill(0, 0);
    int cur = 0;
    for (int tt = 0; tt < nt; tt++) {
        cpa_waitall();
        __syncthreads();
        if (tt + 1 < nt) afill(tt + 1, cur ^ 1);
        if (tt == nt - 1)
            attn_tile<DPHP, TQ, false>(sK[cur], sV[cur], cnt - tt * 128, q2, acc2, l);
        else
            attn_tile<DPHP, TQ, true >(sK[cur], sV[cur], 128, q2, acc2, l);
        cur ^= 1;
    }

    // normalize + direct write to context in (b, q, dim) layout
#pragma unroll
    for (int j = 0; j < TQ; j++) {
        float inv = 1.f / l[j];
        float* cp = C + (size_t)(b * QLEN + qi0 + j) * dim + h * DPH;
#pragma unroll
        for (int i = 0; i < DPH / 2; i++) {
            float lo, hi;
            unpackf2(acc2[j][i], lo, hi);
            *(float2*)(cp + 2 * i) = make_float2(lo * inv, hi * inv);
        }
    }
}

#define NB0 (64 * 4)    // 256
#define NB1 (44 * 4)    // 176

__global__ __launch_bounds__(128) void attn_both()
{
    int bx = blockIdx.x;
    if (bx < NB0)
        attn_body<12, 12, 2, 16>(bx, g_qkv0[0], g_qkv0[1], g_qkv0[2],
                                 &g_cIdx[0][0][0], &g_cnt[0][0], g_c0);
    else
        attn_body<6, 8, 2, 11>(bx - NB0, g_qkv1[0], g_qkv1[1], g_qkv1[2],
                               &g_cIdx[1][0][0], &g_cnt[1][0], g_c1);
}

// ---------------- launch ----------------------------------------------------
extern "C" void kernel_launch(void* const* d_in, const int* in_sizes, int n_in,
                              void* d_out, int out_size)
{
    const float* x     = (const float*)d_in[0];
    const float* y     = (const float*)d_in[1];
    const int*   mask0 = (const int*)d_in[2];
    const int*   mask1 = (const int*)d_in[3];
    const float* q0_w = (const float*)d_in[4],  *q0_b = (const float*)d_in[5];
    const float* k0_w = (const float*)d_in[6],  *k0_b = (const float*)d_in[7];
    const float* v0_w = (const float*)d_in[8],  *v0_b = (const float*)d_in[9];
    const float* o0_w = (const float*)d_in[10], *o0_b = (const float*)d_in[11];
    const float* q1_w = (const float*)d_in[12], *q1_b = (const float*)d_in[13];
    const float* k1_w = (const float*)d_in[14], *k1_b = (const float*)d_in[15];
    const float* v1_w = (const float*)d_in[16], *v1_b = (const float*)d_in[17];
    const float* o1_w = (const float*)d_in[18], *o1_b = (const float*)d_in[19];

    float* out0 = (float*)d_out;
    float* out1 = out0 + (size_t)TOK * 192;

    float *qkv0, *qkv1, *c0, *c1;
    cudaGetSymbolAddress((void**)&qkv0, g_qkv0);
    cudaGetSymbolAddress((void**)&qkv1, g_qkv1);
    cudaGetSymbolAddress((void**)&c0, g_c0);
    cudaGetSymbolAddress((void**)&c1, g_c1);

    const float LOG2E = 1.4426950408889634f;
    const float s0 = LOG2E / sqrtf(12.0f);
    const float s1 = LOG2E / sqrtf(6.0f);

    // fused QKV projections for both MHAs (6 jobs) + compaction slice (z=6)
    GemmJobs jq;
    jq.j[0] = { x, q0_w, q0_b, qkv0,                         192, 192, s0 };
    jq.j[1] = { x, k0_w, k0_b, qkv0 + (size_t)TOK * 192,     192, 192, 1.f };
    jq.j[2] = { x, v0_w, v0_b, qkv0 + (size_t)2 * TOK * 192, 192, 192, 1.f };
    jq.j[3] = { y, q1_w, q1_b, qkv1,                         66,  66,  s1 };
    jq.j[4] = { y, k1_w, k1_b, qkv1 + (size_t)TOK * 66,      66,  66,  1.f };
    jq.j[5] = { y, v1_w, v1_b, qkv1 + (size_t)2 * TOK * 66,  66,  66,  1.f };
    jq.m0 = mask0; jq.m1 = mask1;
    gemm_cp<<<dim3(3, 64, 7), 128>>>(jq);

    // fused attention (both MHAs), cp.async pipelined, tail-bounded
    attn_both<<<NB0 + NB1, 128>>>();

    // fused output projections
    GemmJobs jo;
    jo.j[0] = { c0, o0_w, o0_b, out0, 192, 192, 1.f };
    jo.j[1] = { c1, o1_w, o1_b, out1, 66,  66,  1.f };
    jo.j[2] = jo.j[0]; jo.j[3] = jo.j[0]; jo.j[4] = jo.j[0]; jo.j[5] = jo.j[0];
    jo.m0 = mask0; jo.m1 = mask1;
    gemm_cp<<<dim3(3, 64, 2), 128>>>(jo);
}